// round 6
// baseline (speedup 1.0000x reference)
#include <cuda_runtime.h>
#include <cuda_fp16.h>

#define N_FEAT 96
#define MAX_N  50000
#define MAX_E  800000
#define SCAN_B 256
#define MAX_BLOCKS ((MAX_N + SCAN_B - 1) / SCAN_B)   // 196

// Scratch (device globals; no allocation allowed)
__device__ __half g_xh[MAX_N * N_FEAT];   // fp16 copy of x (gather source, hop 1)
__device__ __half g_h1h[MAX_N * N_FEAT];  // fp16 intermediate (gather source, hop 2)
__device__ int    g_degi[MAX_N];
__device__ float  g_dinv[MAX_N];
__device__ int    g_rowptr[MAX_N + 1];
__device__ int    g_cursor[MAX_N];
__device__ int2   g_csr[MAX_E];           // .x = src, .y = __float_as_int(norm)
__device__ int    g_is64;
__device__ int    g_bsum[MAX_BLOCKS];

// ---------------------------------------------------------------------------
// Fused: zero degi (all blocks) + dtype detection (block 0 only).
// Detection reads only the first 2*E 32-bit words (valid under either dtype):
// int64 -> odd words are high halves of small indices -> all zero;
// int32 -> odd words are random node indices -> essentially never all zero.
__global__ void k_zero_detect(const unsigned int* __restrict__ ei32, int N, int E) {
    int i = blockIdx.x * blockDim.x + threadIdx.x;
    if (i < N) g_degi[i] = 0;
    if (blockIdx.x == 0) {
        __shared__ unsigned int acc;
        if (threadIdx.x == 0) acc = 0u;
        __syncthreads();
        unsigned int v = 0u;
        int W = 2 * E;
        int stride = W / 1024; if (stride < 1) stride = 1;
        for (int k = threadIdx.x; k < 1024; k += blockDim.x) {
            long long w = ((long long)k * stride) | 1;   // odd word
            if (w < W) v |= ei32[w];
        }
        atomicOr(&acc, v);
        __syncthreads();
        if (threadIdx.x == 0) g_is64 = (acc == 0u) ? 1 : 0;
    }
}

// x (fp32) -> g_xh (fp16), vectorized
__global__ void k_half(const float4* __restrict__ x4, int total4) {
    int i = blockIdx.x * blockDim.x + threadIdx.x;
    if (i >= total4) return;
    float4 v = x4[i];
    __half2* o = (__half2*)g_xh;
    o[2 * i]     = __floats2half2_rn(v.x, v.y);
    o[2 * i + 1] = __floats2half2_rn(v.z, v.w);
}

// In-degree count over dst, reading the raw edge buffer (either dtype).
__global__ void k_deg(const void* __restrict__ ei, int E) {
    int e = blockIdx.x * blockDim.x + threadIdx.x;
    if (e >= E) return;
    int d;
    if (g_is64) d = (int)((const long long*)ei)[e + E];
    else        d = ((const int*)ei)[e + E];
    atomicAdd(&g_degi[d], 1);
}

// Per-block sums of degi
__global__ void k_bsum(int N) {
    __shared__ int sh[SCAN_B];
    int i = blockIdx.x * SCAN_B + threadIdx.x;
    sh[threadIdx.x] = (i < N) ? g_degi[i] : 0;
    __syncthreads();
    for (int s = SCAN_B / 2; s > 0; s >>= 1) {
        if (threadIdx.x < s) sh[threadIdx.x] += sh[threadIdx.x + s];
        __syncthreads();
    }
    if (threadIdx.x == 0) g_bsum[blockIdx.x] = sh[0];
}

// Per-block exclusive scan + inline scan of block sums; emit rowptr/cursor/dinv.
__global__ void k_apply(int nblocks, int N) {
    __shared__ int sh[SCAN_B];
    __shared__ int bs[SCAN_B];
    int tid = threadIdx.x;
    // scan the (<=256) block sums redundantly in every block
    int bv = (tid < nblocks) ? g_bsum[tid] : 0;
    bs[tid] = bv;
    __syncthreads();
    for (int d = 1; d < SCAN_B; d <<= 1) {
        int t = (tid >= d) ? bs[tid - d] : 0;
        __syncthreads();
        bs[tid] += t;
        __syncthreads();
    }
    int blockOff = (blockIdx.x > 0) ? bs[blockIdx.x - 1] : 0;   // exclusive
    // local exclusive scan of this block's degi chunk
    int i = blockIdx.x * SCAN_B + tid;
    int dg = (i < N) ? g_degi[i] : 0;
    sh[tid] = dg;
    __syncthreads();
    for (int d = 1; d < SCAN_B; d <<= 1) {
        int t = (tid >= d) ? sh[tid - d] : 0;
        __syncthreads();
        sh[tid] += t;
        __syncthreads();
    }
    if (i < N) {
        int off = blockOff + sh[tid] - dg;
        g_rowptr[i] = off;
        g_cursor[i] = off;
        g_dinv[i]   = rsqrtf((float)(dg + 1));   // +1 for self-loop
    }
    if (i == N - 1) g_rowptr[N] = blockOff + sh[tid];
}

// Scatter edges into CSR-by-dst, packing (src, norm) per slot.
__global__ void k_scatter(const void* __restrict__ ei, int E) {
    int e = blockIdx.x * blockDim.x + threadIdx.x;
    if (e >= E) return;
    int s, d;
    if (g_is64) {
        const long long* p = (const long long*)ei;
        s = (int)p[e]; d = (int)p[e + E];
    } else {
        const int* p = (const int*)ei;
        s = p[e]; d = p[e + E];
    }
    float nrm = g_dinv[s] * g_dinv[d];
    int pos = atomicAdd(&g_cursor[d], 1);
    g_csr[pos] = make_int2(s, __float_as_int(nrm));
}

// ---------------------------------------------------------------------------
// One warp per dst node, fp16 gathers, fp32 accumulation, no atomics.

// hop 1: self from fp32 x, gather from fp16 g_xh, store fp16 g_h1h
__global__ void k_hop1(const float* __restrict__ x, int N) {
    int node = (blockIdx.x * blockDim.x + threadIdx.x) >> 5;
    int lane = threadIdx.x & 31;
    if (node >= N) return;
    int beg = g_rowptr[node];
    int end = g_rowptr[node + 1];
    float di = g_dinv[node];
    float d2 = di * di;
    const float* own = x + (size_t)node * N_FEAT;
    float a0 = d2 * own[lane];
    float a1 = d2 * own[lane + 32];
    float a2 = d2 * own[lane + 64];
    for (int e = beg; e < end; e++) {
        int2 en = g_csr[e];
        const __half* pin = g_xh + (size_t)en.x * N_FEAT;
        float nrm = __int_as_float(en.y);
        a0 += nrm * __half2float(pin[lane]);
        a1 += nrm * __half2float(pin[lane + 32]);
        a2 += nrm * __half2float(pin[lane + 64]);
    }
    __half* po = g_h1h + (size_t)node * N_FEAT;
    po[lane]      = __float2half_rn(a0);
    po[lane + 32] = __float2half_rn(a1);
    po[lane + 64] = __float2half_rn(a2);
}

// hop 2: self + gather from fp16 g_h1h, store fp32 out
__global__ void k_hop2(float* __restrict__ out, int N) {
    int node = (blockIdx.x * blockDim.x + threadIdx.x) >> 5;
    int lane = threadIdx.x & 31;
    if (node >= N) return;
    int beg = g_rowptr[node];
    int end = g_rowptr[node + 1];
    float di = g_dinv[node];
    float d2 = di * di;
    const __half* own = g_h1h + (size_t)node * N_FEAT;
    float a0 = d2 * __half2float(own[lane]);
    float a1 = d2 * __half2float(own[lane + 32]);
    float a2 = d2 * __half2float(own[lane + 64]);
    for (int e = beg; e < end; e++) {
        int2 en = g_csr[e];
        const __half* pin = g_h1h + (size_t)en.x * N_FEAT;
        float nrm = __int_as_float(en.y);
        a0 += nrm * __half2float(pin[lane]);
        a1 += nrm * __half2float(pin[lane + 32]);
        a2 += nrm * __half2float(pin[lane + 64]);
    }
    float* po = out + (size_t)node * N_FEAT;
    po[lane]      = a0;
    po[lane + 32] = a1;
    po[lane + 64] = a2;
}

// ---------------------------------------------------------------------------
extern "C" void kernel_launch(void* const* d_in, const int* in_sizes, int n_in,
                              void* d_out, int out_size) {
    const float* x  = (const float*)d_in[0];
    const void*  ei = d_in[1];
    int N = in_sizes[0] / N_FEAT;      // 50000
    int E = in_sizes[1] / 2;           // 800000
    float* out = (float*)d_out;

    const int T = 256;
    int nScanBlocks = (N + SCAN_B - 1) / SCAN_B;   // 196
    int total4 = N * (N_FEAT / 4);

    k_zero_detect<<<nScanBlocks, SCAN_B>>>((const unsigned int*)ei, N, E);
    k_half   <<<(total4 + T - 1) / T, T>>>((const float4*)x, total4);
    k_deg    <<<(E + T - 1) / T, T>>>(ei, E);
    k_bsum   <<<nScanBlocks, SCAN_B>>>(N);
    k_apply  <<<nScanBlocks, SCAN_B>>>(nScanBlocks, N);
    k_scatter<<<(E + T - 1) / T, T>>>(ei, E);

    int hopBlocks = (N + (T / 32) - 1) / (T / 32);   // one warp per node
    k_hop1<<<hopBlocks, T>>>(x, N);
    k_hop2<<<hopBlocks, T>>>(out, N);
}